// round 11
// baseline (speedup 1.0000x reference)
#include <cuda_runtime.h>
#include <cuda_bf16.h>

// PlotLine2: histogram of rounded lerp points + separable 7-tap Gaussian conv.
// R11: revert to scalar convs (R6 structure, best measured), grid 128 = one
// balanced wave @ 1 CTA/SM, 1024 threads; lerp computed in registers from
// __ldg'd endpoints, overlapped with smem zeroing; atomics-only after barrier.
// Layout: C[iy+3][x] stride 129 (odd), V[t][x+3] stride 135 (odd).

#define N_IMG    128
#define P_PTS    16
#define S_IMG    128
#define D_RAD    3
#define NTAP     7
#define C_STRIDE 129                  // x = 0..128
#define C_ROWS   135                  // r = iy+3, pads r<3 and r>131 stay zero
#define C_SIZE   17416                // 135*129 = 17415, padded to /4
#define V_STRIDE 135                  // col = x+3 (0..134); odd -> conflict-free
#define V_SIZE   (128 * V_STRIDE)     // 17280
#define THREADS  1024
#define NWARP    (THREADS / 32)
#define CHUNK    8
#define WLEN     (CHUNK + NTAP - 1)   // 14

__device__ __forceinline__ float tanh_approx(float x) {
    float r;
    asm("tanh.approx.f32 %0, %1;" : "=f"(r) : "f"(x));
    return r;
}

__global__ __launch_bounds__(THREADS, 1)
void plotline2_kernel(const float* __restrict__ points, float* __restrict__ out) {
    extern __shared__ float sm[];
    float* C = sm;                 // [C_ROWS][C_STRIDE] histogram (row = iy+3)
    float* V = sm + C_SIZE;        // [128][V_STRIDE] y-convolved (col = x+3)

    const int tid  = threadIdx.x;
    const int n    = blockIdx.x;
    const int w    = tid >> 5;
    const int lane = tid & 31;

    // ---- Phase A: zero all smem (vectorized STS.128) while computing lerp
    //      coords in registers from __ldg'd endpoints (overlaps the stores). ----
    int addr0 = -1, addr1 = -1, addr2 = -1, addr3 = -1;
    if (tid < 480) {
        // 4 consecutive samples, all within one segment (4 | j0, j0%128 <= 124)
        int j0  = tid * 4;
        int seg = j0 >> 7;
        int i0  = j0 & (S_IMG - 1);
        const float* pb = points + n * (2 * P_PTS) + seg * 2;
        float p0x = __ldg(pb + 0), p0y = __ldg(pb + 1);
        float p1x = __ldg(pb + 2), p1y = __ldg(pb + 3);
        int a[4];
#pragma unroll
        for (int jj = 0; jj < 4; jj++) {
            // Exact ref arithmetic: t=i/128 exact, non-contracted mul/mul/add,
            // rintf (round-to-nearest-even, matches jnp.round).
            float t   = (float)(i0 + jj) * (1.0f / (float)S_IMG);
            float omt = 1.0f - t;
            float x = __fadd_rn(__fmul_rn(omt, p0x), __fmul_rn(t, p1x));
            float y = __fadd_rn(__fmul_rn(omt, p0y), __fmul_rn(t, p1y));
            int ix = (int)rintf(x);            // 0..128
            int iy = (int)rintf(y);            // 0..128
            a[jj] = (iy + D_RAD) * C_STRIDE + ix;
        }
        addr0 = a[0]; addr1 = a[1]; addr2 = a[2]; addr3 = a[3];
    }
    {
        float4* z = (float4*)sm;
        const float4 z4 = make_float4(0.f, 0.f, 0.f, 0.f);
        for (int i = tid; i < (C_SIZE + V_SIZE) / 4; i += THREADS) z[i] = z4;
    }
    __syncthreads();

    // ---- Phase B: run-length-deduped atomic flush ----
    if (tid < 480) {
        float cnt = 1.0f;
        int   cur = addr0;
        if (addr1 == cur) cnt += 1.0f; else { atomicAdd(&C[cur], cnt); cur = addr1; cnt = 1.0f; }
        if (addr2 == cur) cnt += 1.0f; else { atomicAdd(&C[cur], cnt); cur = addr2; cnt = 1.0f; }
        if (addr3 == cur) cnt += 1.0f; else { atomicAdd(&C[cur], cnt); cur = addr3; cnt = 1.0f; }
        atomicAdd(&C[cur], cnt);
    }
    __syncthreads();

    // Gaussian taps exp(-d^2), d = -3..3 (compile-time -> FFMA immediates)
    const float W[NTAP] = {
        1.2340980408667956e-4f, 1.8315638888734179e-2f, 0.36787944117144233f,
        1.0f,
        0.36787944117144233f,   1.8315638888734179e-2f, 1.2340980408667956e-4f
    };

    // ---- Phase C: convolve along y ----
    // V[t][x+3] = sum_k W[k] * C[t+k][x];  lane -> x (contiguous), slide along t.
    // tasks: xg in 0..4, tc in 0..15 -> 80 tasks over 32 warps
    for (int task = w; task < 80; task += NWARP) {
        int xg = task % 5;
        int tc = task / 5;
        int x  = xg * 32 + lane;
        int t0 = tc * CHUNK;
        if (x < C_STRIDE) {
            float win[WLEN];
#pragma unroll
            for (int j = 0; j < WLEN; j++)
                win[j] = C[(t0 + j) * C_STRIDE + x];
#pragma unroll
            for (int i = 0; i < CHUNK; i++) {
                float a0 = __fmul_rn(W[0], win[i + 0]);
                float a1 = __fmul_rn(W[1], win[i + 1]);
                float a2 = __fmul_rn(W[2], win[i + 2]);
                a0 = fmaf(W[3], win[i + 3], a0);
                a1 = fmaf(W[4], win[i + 4], a1);
                a2 = fmaf(W[5], win[i + 5], a2);
                a0 = fmaf(W[6], win[i + 6], a0);
                V[(t0 + i) * V_STRIDE + (x + D_RAD)] = (a0 + a1) + a2;
            }
        }
    }
    __syncthreads();

    // ---- Phase D: convolve along x, tanh, coalesced write ----
    // out[s][t] = tanh( sum_k W[k] * V[t][s+k] );  lane -> t (stride 135, odd).
    // tasks: tg in 0..3, sc in 0..15 -> 64 tasks over 32 warps (2 each)
    float* o = out + n * (S_IMG * S_IMG);
    for (int task = w; task < 64; task += NWARP) {
        int tg = task & 3;
        int sc = task >> 2;
        int t  = tg * 32 + lane;
        int s0 = sc * CHUNK;
        const float* base = &V[t * V_STRIDE + s0];
        float win[WLEN];
#pragma unroll
        for (int j = 0; j < WLEN; j++) win[j] = base[j];
#pragma unroll
        for (int i = 0; i < CHUNK; i++) {
            float a0 = __fmul_rn(W[0], win[i + 0]);
            float a1 = __fmul_rn(W[1], win[i + 1]);
            float a2 = __fmul_rn(W[2], win[i + 2]);
            a0 = fmaf(W[3], win[i + 3], a0);
            a1 = fmaf(W[4], win[i + 4], a1);
            a2 = fmaf(W[5], win[i + 5], a2);
            a0 = fmaf(W[6], win[i + 6], a0);
            o[(s0 + i) * S_IMG + t] = tanh_approx((a0 + a1) + a2);
        }
    }
}

extern "C" void kernel_launch(void* const* d_in, const int* in_sizes, int n_in,
                              void* d_out, int out_size) {
    const float* points = (const float*)d_in[0];
    float* out = (float*)d_out;
    size_t smem = (size_t)(C_SIZE + V_SIZE) * sizeof(float);
    cudaFuncSetAttribute(plotline2_kernel,
                         cudaFuncAttributeMaxDynamicSharedMemorySize, (int)smem);
    plotline2_kernel<<<N_IMG, THREADS, smem>>>(points, out);
}

// round 13
// speedup vs baseline: 1.0239x; 1.0239x over previous
#include <cuda_runtime.h>
#include <cuda_bf16.h>

// PlotLine2: histogram of rounded lerp points + separable 7-tap Gaussian conv.
// R12: conv order swapped (x-conv first -> A[s][iy+3], y-conv last) so the
// final pass slides along t: 16-float contiguous windows (4x LDS.128) and
// 8 contiguous outputs (2x STG.128). Symmetric taps: 6 fma-pipe ops/output.
// C stride 137 (odd -> conflict-free cross-row LDS); A stride 136 (16B rows).

#define N_IMG    128
#define P_PTS    16
#define S_IMG    128
#define D_RAD    3
#define NTAP     7
#define C_STRIDE 137                  // col = ix+3 (0..133 used), odd
#define C_ROWS   129                  // row = iy (0..128), no y padding needed
#define C_SIZE   17676                // 129*137 = 17673, padded to /4
#define A_STRIDE 136                  // col q = iy+3 (0..135), 544B rows (16B aligned)
#define A_SIZE   (128 * A_STRIDE)     // 17408
#define THREADS  1024

__device__ __forceinline__ float tanh_approx(float x) {
    float r;
    asm("tanh.approx.f32 %0, %1;" : "=f"(r) : "f"(x));
    return r;
}

// symmetric 7-tap: 3 FADD + 3 FFMA
__device__ __forceinline__ float conv7s(const float* win, int i) {
    const float W0 = 1.2340980408667956e-4f;
    const float W1 = 1.8315638888734179e-2f;
    const float W2 = 0.36787944117144233f;
    float s0 = win[i + 0] + win[i + 6];
    float s1 = win[i + 1] + win[i + 5];
    float s2 = win[i + 2] + win[i + 4];
    float r  = fmaf(W2, s2, win[i + 3]);
    r = fmaf(W1, s1, r);
    r = fmaf(W0, s0, r);
    return r;
}

__global__ __launch_bounds__(THREADS, 1)
void plotline2_kernel(const float* __restrict__ points, float* __restrict__ out) {
    extern __shared__ float sm[];
    float* C = sm;                 // [C_ROWS][C_STRIDE] histogram (row=iy, col=ix+3)
    float* A = sm + C_SIZE;        // [128][A_STRIDE] x-convolved (col q = iy+3)

    const int tid = threadIdx.x;
    const int n   = blockIdx.x;

    // ---- Phase A: compute lerp coords in registers (LDG overlapped with the
    //      smem zeroing below). Exact ref arithmetic: t=i/128 exact,
    //      non-contracted mul/mul/add, rintf (RNE like jnp.round). ----
    int addr0 = -1, addr1 = -1, addr2 = -1, addr3 = -1;
    if (tid < 480) {
        int j0  = tid * 4;                 // 4 samples, single segment
        int seg = j0 >> 7;
        int i0  = j0 & (S_IMG - 1);
        const float* pb = points + n * (2 * P_PTS) + seg * 2;
        float p0x = __ldg(pb + 0), p0y = __ldg(pb + 1);
        float p1x = __ldg(pb + 2), p1y = __ldg(pb + 3);
        int a[4];
#pragma unroll
        for (int jj = 0; jj < 4; jj++) {
            float t   = (float)(i0 + jj) * (1.0f / (float)S_IMG);
            float omt = 1.0f - t;
            float x = __fadd_rn(__fmul_rn(omt, p0x), __fmul_rn(t, p1x));
            float y = __fadd_rn(__fmul_rn(omt, p0y), __fmul_rn(t, p1y));
            int ix = (int)rintf(x);        // 0..128
            int iy = (int)rintf(y);        // 0..128
            a[jj] = iy * C_STRIDE + ix + D_RAD;
        }
        addr0 = a[0]; addr1 = a[1]; addr2 = a[2]; addr3 = a[3];
    }
    // zero C (vectorized) + A pad columns only (A interior fully written later)
    {
        float4* z = (float4*)C;
        const float4 z4 = make_float4(0.f, 0.f, 0.f, 0.f);
        for (int i = tid; i < C_SIZE / 4; i += THREADS) z[i] = z4;
    }
    if (tid < 128 * 7) {                   // pad cols q in {0,1,2,132,133,134,135}
        int s  = tid / 7;
        int c7 = tid % 7;
        int q  = (c7 < 3) ? c7 : (129 + c7);
        A[s * A_STRIDE + q] = 0.0f;
    }
    __syncthreads();

    // ---- Phase B: run-length-deduped atomic flush ----
    if (tid < 480) {
        float cnt = 1.0f;
        int   cur = addr0;
        if (addr1 == cur) cnt += 1.0f; else { atomicAdd(&C[cur], cnt); cur = addr1; cnt = 1.0f; }
        if (addr2 == cur) cnt += 1.0f; else { atomicAdd(&C[cur], cnt); cur = addr2; cnt = 1.0f; }
        if (addr3 == cur) cnt += 1.0f; else { atomicAdd(&C[cur], cnt); cur = addr3; cnt = 1.0f; }
        atomicAdd(&C[cur], cnt);
    }
    __syncthreads();

    // ---- Phase C': x-conv.  A[s][iy+3] = sum_k W[k] * C[iy][s+k]  ----
    // thread-task: iy = tt % 129 (lanes -> consecutive rows, odd stride =>
    // conflict-free), s-chunk = tt / 129; per-thread window is same-row.
    for (int tt = tid; tt < 129 * 16; tt += THREADS) {
        int iy = tt % 129;
        int s0 = (tt / 129) * 8;
        const float* base = &C[iy * C_STRIDE + s0];
        float win[14];
#pragma unroll
        for (int j = 0; j < 14; j++) win[j] = base[j];
        float* ac = &A[s0 * A_STRIDE + iy + D_RAD];
#pragma unroll
        for (int i = 0; i < 8; i++)
            ac[i * A_STRIDE] = conv7s(win, i);
    }
    __syncthreads();

    // ---- Phase D': y-conv + tanh + vector store ----
    // out[s][t0+i] = tanh( sum_k W[k] * A[s][t0+i+k] )
    // thread-task: s = tt>>4, tc = tt&15; window = 16 contiguous floats
    // (4x LDS.128, 16B aligned), outputs 8 contiguous floats (2x STG.128).
    float* o = out + n * (S_IMG * S_IMG);
    for (int tt = tid; tt < 128 * 16; tt += THREADS) {
        int s  = tt >> 4;
        int t0 = (tt & 15) * 8;
        const float4* src = (const float4*)&A[s * A_STRIDE + t0];
        float win[16];
#pragma unroll
        for (int q = 0; q < 4; q++) {
            float4 v = src[q];
            win[q * 4 + 0] = v.x; win[q * 4 + 1] = v.y;
            win[q * 4 + 2] = v.z; win[q * 4 + 3] = v.w;
        }
        float res[8];
#pragma unroll
        for (int i = 0; i < 8; i++)
            res[i] = tanh_approx(conv7s(win, i));
        float4* dst = (float4*)&o[s * S_IMG + t0];
        dst[0] = make_float4(res[0], res[1], res[2], res[3]);
        dst[1] = make_float4(res[4], res[5], res[6], res[7]);
    }
}

extern "C" void kernel_launch(void* const* d_in, const int* in_sizes, int n_in,
                              void* d_out, int out_size) {
    const float* points = (const float*)d_in[0];
    float* out = (float*)d_out;
    size_t smem = (size_t)(C_SIZE + A_SIZE) * sizeof(float);
    cudaFuncSetAttribute(plotline2_kernel,
                         cudaFuncAttributeMaxDynamicSharedMemorySize, (int)smem);
    plotline2_kernel<<<N_IMG, THREADS, smem>>>(points, out);
}

// round 16
// speedup vs baseline: 1.2704x; 1.2407x over previous
#include <cuda_runtime.h>
#include <cuda_bf16.h>

// PlotLine2: histogram of rounded lerp points + separable 7-tap Gaussian conv.
// R13 = R11 skeleton (scalar conv, best measured) + symmetric-tap conv
// (6 fma-ops/output), 8-sample run-dedupe (fewer ATOMS), pad-only V zeroing,
// and balanced conv-y tasks. Layout: C[iy+3][x] stride 129, V[t][x+3] stride 135.

#define N_IMG    128
#define P_PTS    16
#define S_IMG    128
#define D_RAD    3
#define C_STRIDE 129                  // x = 0..128
#define C_ROWS   135                  // r = iy+3 (rows 0..2 / 132..134 stay zero)
#define C_SIZE   17416                // 135*129 = 17415, padded to /4
#define V_STRIDE 135                  // col = x+3 (0..134); odd -> conflict-free
#define V_SIZE   (128 * V_STRIDE)     // 17280
#define THREADS  1024
#define NWARP    (THREADS / 32)

__device__ __forceinline__ float tanh_approx(float x) {
    float r;
    asm("tanh.approx.f32 %0, %1;" : "=f"(r) : "f"(x));
    return r;
}

// symmetric 7-tap conv: 3 FADD + 3 FFMA (taps exp(-d^2), d=-3..3)
__device__ __forceinline__ float conv7s(const float* win, int i) {
    const float W0 = 1.2340980408667956e-4f;
    const float W1 = 1.8315638888734179e-2f;
    const float W2 = 0.36787944117144233f;
    float s0 = win[i + 0] + win[i + 6];
    float s1 = win[i + 1] + win[i + 5];
    float s2 = win[i + 2] + win[i + 4];
    float r  = fmaf(W2, s2, win[i + 3]);
    r = fmaf(W1, s1, r);
    r = fmaf(W0, s0, r);
    return r;
}

__global__ __launch_bounds__(THREADS, 1)
void plotline2_kernel(const float* __restrict__ points, float* __restrict__ out) {
    extern __shared__ float sm[];
    float* C = sm;                 // [C_ROWS][C_STRIDE] histogram (row = iy+3)
    float* V = sm + C_SIZE;        // [128][V_STRIDE] y-convolved (col = x+3)

    const int tid  = threadIdx.x;
    const int n    = blockIdx.x;
    const int w    = tid >> 5;
    const int lane = tid & 31;

    // ---- Phase A: lerp coords in registers (LDG + ALU overlap the zeroing).
    //      Exact ref arithmetic: t=i/128 exact, non-contracted mul/mul/add,
    //      rintf = round-to-nearest-even (matches jnp.round). ----
    int a[8];
    if (tid < 240) {
        int j0  = tid * 8;                 // 8 samples, all in one segment
        int seg = j0 >> 7;
        int i0  = j0 & (S_IMG - 1);        // <= 120
        const float* pb = points + n * (2 * P_PTS) + seg * 2;
        float p0x = __ldg(pb + 0), p0y = __ldg(pb + 1);
        float p1x = __ldg(pb + 2), p1y = __ldg(pb + 3);
#pragma unroll
        for (int jj = 0; jj < 8; jj++) {
            float t   = (float)(i0 + jj) * (1.0f / (float)S_IMG);
            float omt = 1.0f - t;
            float x = __fadd_rn(__fmul_rn(omt, p0x), __fmul_rn(t, p1x));
            float y = __fadd_rn(__fmul_rn(omt, p0y), __fmul_rn(t, p1y));
            int ix = (int)rintf(x);        // 0..128
            int iy = (int)rintf(y);        // 0..128
            a[jj] = (iy + D_RAD) * C_STRIDE + ix;
        }
    }
    // zero C (vectorized) + V pad columns only (interior fully written in phase C)
    {
        float4* z = (float4*)C;
        const float4 z4 = make_float4(0.f, 0.f, 0.f, 0.f);
        for (int i = tid; i < C_SIZE / 4; i += THREADS) z[i] = z4;
    }
    if (tid < 128 * 6) {                   // pad cols 0..2 and 132..134
        int t  = tid / 6;
        int c6 = tid % 6;
        int c  = (c6 < 3) ? c6 : (129 + c6);
        V[t * V_STRIDE + c] = 0.0f;
    }
    __syncthreads();

    // ---- Phase B: run-length-deduped atomic flush (8-sample runs) ----
    if (tid < 240) {
        float cnt = 1.0f;
        int   cur = a[0];
#pragma unroll
        for (int jj = 1; jj < 8; jj++) {
            if (a[jj] == cur) { cnt += 1.0f; }
            else { atomicAdd(&C[cur], cnt); cur = a[jj]; cnt = 1.0f; }
        }
        atomicAdd(&C[cur], cnt);
    }
    __syncthreads();

    // ---- Phase C: convolve along y ----
    // V[t][x+3] = sum_k W[k] * C[t+k][x]
    // tasks 0..63: lane -> x in 0..127 (4 full groups), slide along t (8 outs)
    // tasks 64..67: x = 128 sliver, lane -> t
    for (int task = w; task < 68; task += NWARP) {
        if (task < 64) {
            int x  = (task & 3) * 32 + lane;
            int t0 = (task >> 2) * 8;
            float win[14];
#pragma unroll
            for (int j = 0; j < 14; j++)
                win[j] = C[(t0 + j) * C_STRIDE + x];
#pragma unroll
            for (int i = 0; i < 8; i++)
                V[(t0 + i) * V_STRIDE + (x + D_RAD)] = conv7s(win, i);
        } else {
            int t = (task - 64) * 32 + lane;       // 0..127
            float win[7];
#pragma unroll
            for (int j = 0; j < 7; j++)
                win[j] = C[(t + j) * C_STRIDE + 128];
            V[t * V_STRIDE + 131] = conv7s(win, 0);
        }
    }
    __syncthreads();

    // ---- Phase D: convolve along x, tanh, warp-coalesced scalar stores ----
    // out[s][t] = tanh( sum_k W[k] * V[t][s+k] );  lane -> t (stride 135, odd),
    // thread slides along s: each STG.32 is a full 128B coalesced line.
    float* o = out + n * (S_IMG * S_IMG);
    for (int task = w; task < 64; task += NWARP) {
        int tg = task & 3;
        int sc = task >> 2;
        int t  = tg * 32 + lane;
        int s0 = sc * 8;
        const float* base = &V[t * V_STRIDE + s0];
        float win[14];
#pragma unroll
        for (int j = 0; j < 14; j++) win[j] = base[j];
#pragma unroll
        for (int i = 0; i < 8; i++)
            o[(s0 + i) * S_IMG + t] = tanh_approx(conv7s(win, i));
    }
}

extern "C" void kernel_launch(void* const* d_in, const int* in_sizes, int n_in,
                              void* d_out, int out_size) {
    const float* points = (const float*)d_in[0];
    float* out = (float*)d_out;
    size_t smem = (size_t)(C_SIZE + V_SIZE) * sizeof(float);
    cudaFuncSetAttribute(plotline2_kernel,
                         cudaFuncAttributeMaxDynamicSharedMemorySize, (int)smem);
    plotline2_kernel<<<N_IMG, THREADS, smem>>>(points, out);
}